// round 9
// baseline (speedup 1.0000x reference)
#include <cuda_runtime.h>
#include <cuda_bf16.h>
#include <cstdint>

// NnInteractionTokenizer: bond = x[row]*x[col]; local_field = segsum(bond, row);
// tokens = relu(relu([x, lf] @ w1^T + b1) @ w2^T + b2)
//
// local_field[r] = x[r] * sum_{e: row[e]=r} x[col[e]] -> edge phase only
// accumulates x[col[e]] into g_acc[row[e]]; x[r] multiply folds into node phase.
//
// R9: single persistent kernel (148 CTAs x 1024 thr -> all resident in wave 1,
// software grid barrier is safe). Edge inner loop identical to R7 (measured
// floor: shared LSU/L1tex pipe, gather-wavefronts + spread-REDG). Node phase
// fused after the barrier: no 2nd launch, weights pre-staged, g_acc L2-hot.
//
// g_acc invariant: zeroed at module load; node phase re-zeroes each g_acc[n]
// from the SAME thread that read it -> zero at entry of every graph replay.
// g_bar is a monotonic arrival counter (never reset; target derived from the
// pre-increment value, wrap-safe) -> replay-safe barrier.

#define N_NODES 100000
#define N_EDGES 6400000
#define TD 16
#define EPT 4
#define BLK 1024
#define GRID 148
#define CHUNK (BLK * EPT)                           // 4096 edges per chunk
#define NCHUNKS ((N_EDGES + CHUNK - 1) / CHUNK)     // 1563

__device__ float g_acc[N_NODES];
__device__ unsigned int g_bar;    // monotonic across replays

__global__ void __launch_bounds__(BLK, 1)
fused_kernel(const void* __restrict__ ei, const float* __restrict__ x,
             const float* __restrict__ w1, const float* __restrict__ b1,
             const float* __restrict__ w2, const float* __restrict__ b2,
             float* __restrict__ out) {
    __shared__ float sw1[2 * TD];
    __shared__ float sb1[TD];
    __shared__ __align__(16) float sw2[TD * TD];
    __shared__ float sb2[TD];
    __shared__ int s_is64;

    const int t = threadIdx.x;

    // Stage MLP weights up front (overlaps edge phase issue).
    if (t < 2 * TD) sw1[t] = w1[t];
    if (t < TD) { sb1[t] = b1[t]; sb2[t] = b2[t]; }
    if (t < TD * TD) sw2[t] = w2[t];

    // Dtype probe (uniform): int64 edge data (< 2^17, LE) has all odd uint32
    // words zero; int32 data has random words -> P(8 zeros) ~ 1e-40.
    if (t == 0) {
        const unsigned int* w = (const unsigned int*)ei;
        unsigned int acc = 0;
#pragma unroll
        for (int k = 0; k < 8; k++) acc |= w[2 * k + 1];
        s_is64 = (acc == 0u) ? 1 : 0;
    }
    __syncthreads();
    const int is64 = s_is64;

    // ---------------- edge phase (R7 inner loop, chunk-strided) -------------
    for (int c = blockIdx.x; c < NCHUNKS; c += GRID) {
        const long long base = (long long)c * CHUNK + (long long)t * EPT;
        if (base >= N_EDGES) continue;

        int r[EPT], cl[EPT];
        if (is64) {
            const longlong2* row = (const longlong2*)ei;       // edge_index[0]
            const longlong2* col = row + (N_EDGES / 2);        // edge_index[1]
            longlong2 r0 = __ldg(&row[base / 2]);
            longlong2 r1 = __ldg(&row[base / 2 + 1]);
            longlong2 c0 = __ldg(&col[base / 2]);
            longlong2 c1 = __ldg(&col[base / 2 + 1]);
            r[0] = (int)r0.x; r[1] = (int)r0.y; r[2] = (int)r1.x; r[3] = (int)r1.y;
            cl[0] = (int)c0.x; cl[1] = (int)c0.y; cl[2] = (int)c1.x; cl[3] = (int)c1.y;
        } else {
            const int4* row = (const int4*)ei;
            const int4* col = row + (N_EDGES / 4);
            int4 rv = __ldg(&row[base / 4]);
            int4 cv = __ldg(&col[base / 4]);
            r[0] = rv.x; r[1] = rv.y; r[2] = rv.z; r[3] = rv.w;
            cl[0] = cv.x; cl[1] = cv.y; cl[2] = cv.z; cl[3] = cv.w;
        }

        float v[EPT];
#pragma unroll
        for (int k = 0; k < EPT; k++) v[k] = __ldg(&x[cl[k]]);
#pragma unroll
        for (int k = 0; k < EPT; k++) atomicAdd(&g_acc[r[k]], v[k]);
    }

    // ---------------- grid barrier (monotonic counter, replay-safe) ---------
    __threadfence();            // publish this thread's REDs before signaling
    __syncthreads();
    if (t == 0) {
        unsigned int old = atomicAdd(&g_bar, 1u);
        unsigned int target = old - (old % GRID) + GRID;
        volatile unsigned int* p = &g_bar;
        while ((int)(*p - target) < 0) { }
    }
    __syncthreads();
    __threadfence();            // order subsequent g_acc loads after release

    // ---------------- node phase (R7 logic, 1 thread per node) --------------
    const int n = blockIdx.x * BLK + t;
    if (n >= N_NODES) return;

    const float s  = x[n];
    const float lfa = g_acc[n];
    g_acc[n] = 0.0f;            // same thread, same address: ordered after read

    const float lf = s * lfa;

    float h[TD];
#pragma unroll
    for (int j = 0; j < TD; j++) {
        float v = fmaf(sw1[2 * j + 1], lf, fmaf(sw1[2 * j], s, sb1[j]));
        h[j] = v > 0.f ? v : 0.f;
    }

    float4* o = (float4*)(out + (size_t)n * TD);
#pragma unroll
    for (int k4 = 0; k4 < 4; k4++) {
        float4 res;
        float* rp = (float*)&res;
#pragma unroll
        for (int kk = 0; kk < 4; kk++) {
            const int k = k4 * 4 + kk;
            float v = sb2[k];
            const float4* wrow = (const float4*)&sw2[k * TD];
#pragma unroll
            for (int j4 = 0; j4 < 4; j4++) {
                float4 w = wrow[j4];
                v = fmaf(w.x, h[j4 * 4 + 0], v);
                v = fmaf(w.y, h[j4 * 4 + 1], v);
                v = fmaf(w.z, h[j4 * 4 + 2], v);
                v = fmaf(w.w, h[j4 * 4 + 3], v);
            }
            rp[kk] = v > 0.f ? v : 0.f;
        }
        o[k4] = res;
    }
}

extern "C" void kernel_launch(void* const* d_in, const int* in_sizes, int n_in,
                              void* d_out, int out_size) {
    const float* x  = (const float*)d_in[0];
    const void*  ei = d_in[1];
    const float* w1 = (const float*)d_in[2];
    const float* b1 = (const float*)d_in[3];
    const float* w2 = (const float*)d_in[4];
    const float* b2 = (const float*)d_in[5];
    float* out = (float*)d_out;

    fused_kernel<<<GRID, BLK>>>(ei, x, w1, b1, w2, b2, out);
}

// round 11
// speedup vs baseline: 1.2687x; 1.2687x over previous
#include <cuda_runtime.h>
#include <cuda_bf16.h>
#include <cstdint>

// NnInteractionTokenizer: bond = x[row]*x[col]; local_field = segsum(bond, row);
// tokens = relu(relu([x, lf] @ w1^T + b1) @ w2^T + b2)
//
// local_field[r] = x[r] * sum_{e: row[e]=r} x[col[e]] -> edge phase only
// accumulates x[col[e]] into g_acc[row[e]]; x[r] multiply folds into node phase.
//
// R10/R11: two kernels (R9 fusion regressed: 1024-thr CTA ate the whole RF ->
// occ 50%, issue 4.6% -> edge is LATENCY-bound on divergent gathers, L2 had
// headroom). Edge kernel __launch_bounds__(256, 8): <=32 regs -> 8 CTAs/SM
// = 64 warps = 100% occ for maximum gather/atomic latency hiding.
//
// g_acc invariant: __device__ globals start zeroed; node_kernel re-zeroes
// g_acc[n] from the SAME thread that read it (same-addr program order, no
// barrier) -> g_acc == 0 at entry of every kernel_launch / graph replay.

#define N_NODES 100000
#define N_EDGES 6400000
#define TD 16
#define EPT 4

__device__ float g_acc[N_NODES];

// ---------------------------------------------------------------------------
// Edge phase: EPT edges/thread; vectorized index loads (DRAM stream), batched
// divergent gathers (L1/L2), EPT fire-and-forget REDG.F32 into g_acc.
//
// Dtype probe (per block, uniform): reference asks int64 but JAX w/o x64
// yields int32 (confirmed by measured HBM traffic ~51MB). As uint32 words,
// int64 data (<2^17, LE) has odd words == 0; int32 data has random words ->
// P(8 specific odd words all zero) ~ 1e-40. All blocks read the SAME 8 words
// (L2 broadcast) -> globally uniform decision.
// ---------------------------------------------------------------------------
__global__ void __launch_bounds__(256, 8) edge_kernel(const void* __restrict__ ei,
                                                      const float* __restrict__ x) {
    __shared__ int s_is64;
    if (threadIdx.x == 0) {
        const unsigned int* w = (const unsigned int*)ei;
        unsigned int acc = 0;
#pragma unroll
        for (int k = 0; k < 8; k++) acc |= w[2 * k + 1];
        s_is64 = (acc == 0u) ? 1 : 0;
    }
    __syncthreads();

    const int tid = blockIdx.x * blockDim.x + threadIdx.x;
    const long long base = (long long)tid * EPT;
    if (base >= N_EDGES) return;

    if (!s_is64) {
        // int32 path (the measured-real one): kept lean for <=32 regs.
        const int4* row = (const int4*)ei;
        const int4* col = row + (N_EDGES / 4);
        int4 rv = __ldg(&row[base / 4]);
        int4 cv = __ldg(&col[base / 4]);

        float v0 = __ldg(&x[cv.x]);
        float v1 = __ldg(&x[cv.y]);
        float v2 = __ldg(&x[cv.z]);
        float v3 = __ldg(&x[cv.w]);

        atomicAdd(&g_acc[rv.x], v0);
        atomicAdd(&g_acc[rv.y], v1);
        atomicAdd(&g_acc[rv.z], v2);
        atomicAdd(&g_acc[rv.w], v3);
    } else {
        const longlong2* row = (const longlong2*)ei;          // edge_index[0]
        const longlong2* col = row + (N_EDGES / 2);           // edge_index[1]
        longlong2 r0 = __ldg(&row[base / 2]);
        longlong2 r1 = __ldg(&row[base / 2 + 1]);
        longlong2 c0 = __ldg(&col[base / 2]);
        longlong2 c1 = __ldg(&col[base / 2 + 1]);

        float v0 = __ldg(&x[(int)c0.x]);
        float v1 = __ldg(&x[(int)c0.y]);
        float v2 = __ldg(&x[(int)c1.x]);
        float v3 = __ldg(&x[(int)c1.y]);

        atomicAdd(&g_acc[(int)r0.x], v0);
        atomicAdd(&g_acc[(int)r0.y], v1);
        atomicAdd(&g_acc[(int)r1.x], v2);
        atomicAdd(&g_acc[(int)r1.y], v3);
    }
}

// ---------------------------------------------------------------------------
// Node phase (R7 form, measured 7.4us): 1 thread/node; x/g_acc loads issued
// before the weight barrier; same-thread g_acc read->clear; LDS.128 weights.
// ---------------------------------------------------------------------------
__global__ void __launch_bounds__(256) node_kernel(const float* __restrict__ x,
                                                   const float* __restrict__ w1,
                                                   const float* __restrict__ b1,
                                                   const float* __restrict__ w2,
                                                   const float* __restrict__ b2,
                                                   float* __restrict__ out) {
    __shared__ float sw1[2 * TD];
    __shared__ float sb1[TD];
    __shared__ __align__(16) float sw2[TD * TD];
    __shared__ float sb2[TD];

    const int t = threadIdx.x;
    const int n = blockIdx.x * 256 + t;
    const bool act = (n < N_NODES);

    float s = 0.f, lfa = 0.f;
    if (act) { s = x[n]; lfa = g_acc[n]; }

    if (t < 2 * TD) sw1[t] = w1[t];
    if (t < TD) { sb1[t] = b1[t]; sb2[t] = b2[t]; }
    sw2[t] = w2[t];   // blockDim == 256 == TD*TD
    __syncthreads();

    if (act) g_acc[n] = 0.0f;   // same thread, same address: ordered after read

    const float lf = s * lfa;

    float h[TD];
#pragma unroll
    for (int j = 0; j < TD; j++) {
        float v = fmaf(sw1[2 * j + 1], lf, fmaf(sw1[2 * j], s, sb1[j]));
        h[j] = v > 0.f ? v : 0.f;
    }

    float4* o = (float4*)(out + (size_t)n * TD);
#pragma unroll
    for (int k4 = 0; k4 < 4; k4++) {
        float4 res;
        float* rp = (float*)&res;
#pragma unroll
        for (int kk = 0; kk < 4; kk++) {
            const int k = k4 * 4 + kk;
            float v = sb2[k];
            const float4* wrow = (const float4*)&sw2[k * TD];
#pragma unroll
            for (int j4 = 0; j4 < 4; j4++) {
                float4 w = wrow[j4];
                v = fmaf(w.x, h[j4 * 4 + 0], v);
                v = fmaf(w.y, h[j4 * 4 + 1], v);
                v = fmaf(w.z, h[j4 * 4 + 2], v);
                v = fmaf(w.w, h[j4 * 4 + 3], v);
            }
            rp[kk] = v > 0.f ? v : 0.f;
        }
        if (act) o[k4] = res;
    }
}

extern "C" void kernel_launch(void* const* d_in, const int* in_sizes, int n_in,
                              void* d_out, int out_size) {
    const float* x  = (const float*)d_in[0];
    const void*  ei = d_in[1];
    const float* w1 = (const float*)d_in[2];
    const float* b1 = (const float*)d_in[3];
    const float* w2 = (const float*)d_in[4];
    const float* b2 = (const float*)d_in[5];
    float* out = (float*)d_out;

    edge_kernel<<<N_EDGES / EPT / 256, 256>>>(ei, x);
    node_kernel<<<(N_NODES + 255) / 256, 256>>>(x, w1, b1, w2, b2, out);
}